// round 6
// baseline (speedup 1.0000x reference)
#include <cuda_runtime.h>

#define H 4096
#define NIN 17
#define NA 4

#define GRID1 1024          // K1: 4 rows per block
#define T1 512
#define GRID2 32            // K2: 128 cols per block
#define T2 512
#define GRID3 1024          // K3: 4 rows per block (+1 head block)
#define T3 512

// persistent device scratch (static globals allowed; no runtime alloc)
__device__ float4 g_scratch4[GRID1 * H / 4];   // [p][col/4] partial sums, 16 MiB
__device__ __align__(16) float g_h[H];         // aligned shadow of h

// ---- 256-bit L2-eviction-hinted loads (sm_100+: hints require .v4.b64/.v8.b32) ----
__device__ __forceinline__ void ldg8_ef(const float* p, float v[8]) {
    unsigned long long r0, r1, r2, r3;
    asm volatile("ld.global.L2::evict_first.v4.b64 {%0,%1,%2,%3}, [%4];"
                 : "=l"(r0), "=l"(r1), "=l"(r2), "=l"(r3) : "l"(p));
    v[0] = __uint_as_float((unsigned)r0); v[1] = __uint_as_float((unsigned)(r0 >> 32));
    v[2] = __uint_as_float((unsigned)r1); v[3] = __uint_as_float((unsigned)(r1 >> 32));
    v[4] = __uint_as_float((unsigned)r2); v[5] = __uint_as_float((unsigned)(r2 >> 32));
    v[6] = __uint_as_float((unsigned)r3); v[7] = __uint_as_float((unsigned)(r3 >> 32));
}
__device__ __forceinline__ void ldg8_el(const float* p, float v[8]) {
    unsigned long long r0, r1, r2, r3;
    asm volatile("ld.global.L2::evict_last.v4.b64 {%0,%1,%2,%3}, [%4];"
                 : "=l"(r0), "=l"(r1), "=l"(r2), "=l"(r3) : "l"(p));
    v[0] = __uint_as_float((unsigned)r0); v[1] = __uint_as_float((unsigned)(r0 >> 32));
    v[2] = __uint_as_float((unsigned)r1); v[3] = __uint_as_float((unsigned)(r1 >> 32));
    v[4] = __uint_as_float((unsigned)r2); v[5] = __uint_as_float((unsigned)(r2 >> 32));
    v[6] = __uint_as_float((unsigned)r3); v[7] = __uint_as_float((unsigned)(r3 >> 32));
}

// ============ K1: partial sums of hidden @ (w + alpha*hebb), 4 rows/block ============
__global__ __launch_bounds__(T1)
void k1_partials(const float* __restrict__ hidden,
                 const float* __restrict__ w,
                 const float* __restrict__ alpha,
                 const float* __restrict__ hebb)
{
    const int tid = threadIdx.x;
    const int p   = blockIdx.x;
    const int i0  = p * 4;
    const int c0  = tid * 8;          // this thread's 8-column chunk (32B aligned)

    float acc[8] = {0.f, 0.f, 0.f, 0.f, 0.f, 0.f, 0.f, 0.f};
    #pragma unroll
    for (int r = 0; r < 4; ++r) {
        const float hv = __ldg(&hidden[i0 + r]);
        const size_t off = (size_t)(i0 + r) * H + c0;
        float wv[8], av[8], hb[8];
        ldg8_ef(w     + off, wv);
        ldg8_ef(alpha + off, av);
        ldg8_el(hebb  + off, hb);     // keep hebb resident in L2 for K3
        #pragma unroll
        for (int c = 0; c < 8; ++c)
            acc[c] = fmaf(hv, fmaf(av[c], hb[c], wv[c]), acc[c]);
    }
    float4* s = &g_scratch4[((size_t)p * H + c0) / 4];
    s[0] = make_float4(acc[0], acc[1], acc[2], acc[3]);
    s[1] = make_float4(acc[4], acc[5], acc[6], acc[7]);
}

// ============ K2: reduce 1024 partials per column, i2h + tanh -> h ============
__global__ __launch_bounds__(T2)
void k2_reduce(const float* __restrict__ x,
               const float* __restrict__ i2h_w,
               const float* __restrict__ i2h_b,
               float* __restrict__ out)
{
    __shared__ float4 sred[16][32];
    const int tid   = threadIdx.x;
    const int q     = tid & 31;        // local quad (4 cols)
    const int s     = tid >> 5;        // slice (warp)
    const int qbase = blockIdx.x * 32;

    float4 acc = make_float4(0.f, 0.f, 0.f, 0.f);
    #pragma unroll 4
    for (int p = s; p < GRID1; p += 16) {
        const float4 v = g_scratch4[(size_t)p * (H / 4) + qbase + q];
        acc.x += v.x; acc.y += v.y; acc.z += v.z; acc.w += v.w;
    }
    sred[s][q] = acc;
    __syncthreads();

    if (tid < 32) {
        float4 pre = sred[0][tid];
        #pragma unroll
        for (int t = 1; t < 16; ++t) {
            const float4 v = sred[t][tid];
            pre.x += v.x; pre.y += v.y; pre.z += v.z; pre.w += v.w;
        }
        const int j0 = (qbase + tid) * 4;
        const float* prep = &pre.x;
        #pragma unroll
        for (int c = 0; c < 4; ++c) {
            const int j = j0 + c;
            float pr = i2h_b[j];
            #pragma unroll
            for (int kk = 0; kk < NIN; ++kk)
                pr = fmaf(x[kk], i2h_w[j * NIN + kk], pr);
            const float hj = tanhf(pr + prep[c]);
            out[5 + j] = hj;        // user-visible h
            g_h[j]     = hj;        // aligned shadow for K3 vector reads
        }
    }
}

// ============ K3: block 0 = heads; blocks 1..GRID3 = hebb_new update ============
__global__ __launch_bounds__(T3)
void k3_hebb(const float* __restrict__ hebb,
             const float* __restrict__ hidden,
             const float* __restrict__ eta,
             const float* __restrict__ h2o_w,
             const float* __restrict__ h2o_b,
             const float* __restrict__ h2v_w,
             const float* __restrict__ h2v_b,
             float* __restrict__ out)
{
    const int tid = threadIdx.x;

    if (blockIdx.x == 0) {
        // ----- heads: 5 dot products + softmax (deterministic fixed-order reduce) -----
        __shared__ float red[16][NA + 1];
        __shared__ float logits[NA + 1];
        const int warp = tid >> 5, lane = tid & 31;
        float acc[NA + 1] = {0.f, 0.f, 0.f, 0.f, 0.f};
        #pragma unroll
        for (int k = 0; k < H / T3; ++k) {
            const int j = tid + k * T3;
            const float hv = g_h[j];
            acc[0] = fmaf(hv, h2o_w[0 * H + j], acc[0]);
            acc[1] = fmaf(hv, h2o_w[1 * H + j], acc[1]);
            acc[2] = fmaf(hv, h2o_w[2 * H + j], acc[2]);
            acc[3] = fmaf(hv, h2o_w[3 * H + j], acc[3]);
            acc[4] = fmaf(hv, h2v_w[j],         acc[4]);
        }
        #pragma unroll
        for (int a = 0; a < NA + 1; ++a) {
            #pragma unroll
            for (int o = 16; o; o >>= 1)
                acc[a] += __shfl_xor_sync(0xffffffffu, acc[a], o);
            if (lane == 0) red[warp][a] = acc[a];
        }
        __syncthreads();
        if (tid < NA + 1) {
            float s = (tid < NA) ? h2o_b[tid] : h2v_b[0];
            #pragma unroll
            for (int wp = 0; wp < 16; ++wp) s += red[wp][tid];
            logits[tid] = s;
        }
        __syncthreads();
        if (tid == 0) {
            float m = logits[0];
            #pragma unroll
            for (int a = 1; a < NA; ++a) m = fmaxf(m, logits[a]);
            float e[NA], se = 0.f;
            #pragma unroll
            for (int a = 0; a < NA; ++a) { e[a] = expf(logits[a] - m); se += e[a]; }
            const float inv = 1.f / se;
            #pragma unroll
            for (int a = 0; a < NA; ++a) out[a] = e[a] * inv;
            out[NA] = logits[NA];
        }
        return;
    }

    // ----- hebb update: 4 rows per block, reversed so L2-hot rows go first -----
    const int chunk = GRID3 - blockIdx.x;       // 1023..0
    const size_t base8 = (size_t)chunk * 2048;  // 8-float chunks; 2048 per 4 rows
    const float eta_v = __ldg(eta);
    const float om    = 1.f - eta_v;
    const float4* __restrict__ h4p = (const float4*)g_h;
    float* __restrict__ outp = out + 5 + H;     // 4B-misaligned rows -> scalar stores

    #pragma unroll
    for (int k = 0; k < 4; ++k) {
        const size_t n8 = base8 + (size_t)k * T3 + tid;
        const int i = (int)(n8 >> 9);           // row (512 chunks per row)
        const int j = (int)(n8 & 511) * 8;      // column
        float hb[8];
        ldg8_ef(hebb + n8 * 8, hb);
        const float4 h4a = h4p[j / 4];
        const float4 h4b = h4p[j / 4 + 1];
        const float ev = eta_v * __ldg(&hidden[i]);
        float* o = outp + n8 * 8;
        o[0] = fmaf(om, hb[0], ev * h4a.x);
        o[1] = fmaf(om, hb[1], ev * h4a.y);
        o[2] = fmaf(om, hb[2], ev * h4a.z);
        o[3] = fmaf(om, hb[3], ev * h4a.w);
        o[4] = fmaf(om, hb[4], ev * h4b.x);
        o[5] = fmaf(om, hb[5], ev * h4b.y);
        o[6] = fmaf(om, hb[6], ev * h4b.z);
        o[7] = fmaf(om, hb[7], ev * h4b.w);
    }
}

extern "C" void kernel_launch(void* const* d_in, const int* in_sizes, int n_in,
                              void* d_out, int out_size)
{
    const float* x      = (const float*)d_in[0];
    const float* hidden = (const float*)d_in[1];
    const float* hebb   = (const float*)d_in[2];
    const float* i2h_w  = (const float*)d_in[3];
    const float* i2h_b  = (const float*)d_in[4];
    const float* w      = (const float*)d_in[5];
    const float* alpha  = (const float*)d_in[6];
    const float* eta    = (const float*)d_in[7];
    const float* h2o_w  = (const float*)d_in[8];
    const float* h2o_b  = (const float*)d_in[9];
    const float* h2v_w  = (const float*)d_in[10];
    const float* h2v_b  = (const float*)d_in[11];
    float* out = (float*)d_out;

    k1_partials<<<GRID1, T1>>>(hidden, w, alpha, hebb);
    k2_reduce  <<<GRID2, T2>>>(x, i2h_w, i2h_b, out);
    k3_hebb    <<<GRID3 + 1, T3>>>(hebb, hidden, eta, h2o_w, h2o_b, h2v_w, h2v_b, out);
}

// round 7
// speedup vs baseline: 1.7746x; 1.7746x over previous
#include <cuda_runtime.h>

#define H 4096
#define NIN 17
#define NA 4

#define GRID1 512           // K1: 8 rows per block
#define T1 512
#define GRID2 128           // K2: 32 cols per block
#define T2 512
#define GRID3 1024          // K3: 16384 elements per block (+1 head block)
#define T3 512

// persistent device scratch (static globals allowed; no runtime alloc)
__device__ float4 g_scratch4[GRID1 * H / 4];   // [p][col/4] partials, 8 MiB
__device__ __align__(16) float g_h[H];         // aligned shadow of h

// ---- 256-bit L2-eviction-hinted loads (sm_100+: hints require .v4.b64/.v8.b32) ----
__device__ __forceinline__ void ldg8_ef(const float* p, float v[8]) {
    unsigned long long r0, r1, r2, r3;
    asm volatile("ld.global.L2::evict_first.v4.b64 {%0,%1,%2,%3}, [%4];"
                 : "=l"(r0), "=l"(r1), "=l"(r2), "=l"(r3) : "l"(p));
    v[0] = __uint_as_float((unsigned)r0); v[1] = __uint_as_float((unsigned)(r0 >> 32));
    v[2] = __uint_as_float((unsigned)r1); v[3] = __uint_as_float((unsigned)(r1 >> 32));
    v[4] = __uint_as_float((unsigned)r2); v[5] = __uint_as_float((unsigned)(r2 >> 32));
    v[6] = __uint_as_float((unsigned)r3); v[7] = __uint_as_float((unsigned)(r3 >> 32));
}
__device__ __forceinline__ void ldg8_el(const float* p, float v[8]) {
    unsigned long long r0, r1, r2, r3;
    asm volatile("ld.global.L2::evict_last.v4.b64 {%0,%1,%2,%3}, [%4];"
                 : "=l"(r0), "=l"(r1), "=l"(r2), "=l"(r3) : "l"(p));
    v[0] = __uint_as_float((unsigned)r0); v[1] = __uint_as_float((unsigned)(r0 >> 32));
    v[2] = __uint_as_float((unsigned)r1); v[3] = __uint_as_float((unsigned)(r1 >> 32));
    v[4] = __uint_as_float((unsigned)r2); v[5] = __uint_as_float((unsigned)(r2 >> 32));
    v[6] = __uint_as_float((unsigned)r3); v[7] = __uint_as_float((unsigned)(r3 >> 32));
}

// ============ K1: partial sums of hidden @ (w + alpha*hebb), 8 rows/block ============
__global__ __launch_bounds__(T1)
void k1_partials(const float* __restrict__ hidden,
                 const float* __restrict__ w,
                 const float* __restrict__ alpha,
                 const float* __restrict__ hebb)
{
    const int tid = threadIdx.x;
    const int p   = blockIdx.x;
    const int i0  = p * 8;
    const int c0  = tid * 8;          // this thread's 8-column chunk (32B aligned)

    float acc[8] = {0.f, 0.f, 0.f, 0.f, 0.f, 0.f, 0.f, 0.f};
    #pragma unroll
    for (int r = 0; r < 8; ++r) {
        const float hv = __ldg(&hidden[i0 + r]);
        const size_t off = (size_t)(i0 + r) * H + c0;
        float wv[8], av[8], hb[8];
        ldg8_ef(w     + off, wv);
        ldg8_ef(alpha + off, av);
        ldg8_el(hebb  + off, hb);     // keep hebb resident in L2 for K3
        #pragma unroll
        for (int c = 0; c < 8; ++c)
            acc[c] = fmaf(hv, fmaf(av[c], hb[c], wv[c]), acc[c]);
    }
    float4* s = &g_scratch4[((size_t)p * H + c0) / 4];
    s[0] = make_float4(acc[0], acc[1], acc[2], acc[3]);
    s[1] = make_float4(acc[4], acc[5], acc[6], acc[7]);
}

// ============ K2: reduce 512 partials per column, i2h + tanh -> h ============
__global__ __launch_bounds__(T2)
void k2_reduce(const float* __restrict__ x,
               const float* __restrict__ i2h_w,
               const float* __restrict__ i2h_b,
               float* __restrict__ out)
{
    __shared__ float4 sred[64][8];
    const int tid   = threadIdx.x;
    const int q     = tid & 7;         // local quad (4 cols), 8 quads = 32 cols
    const int s     = tid >> 3;        // slice 0..63
    const int qbase = blockIdx.x * 8;  // 32 columns per block

    float4 acc = make_float4(0.f, 0.f, 0.f, 0.f);
    #pragma unroll
    for (int p = s; p < GRID1; p += 64) {
        const float4 v = g_scratch4[(size_t)p * (H / 4) + qbase + q];
        acc.x += v.x; acc.y += v.y; acc.z += v.z; acc.w += v.w;
    }
    sred[s][q] = acc;
    __syncthreads();

    if (tid < 8) {
        float4 pre = sred[0][tid];
        #pragma unroll
        for (int t = 1; t < 64; ++t) {
            const float4 v = sred[t][tid];
            pre.x += v.x; pre.y += v.y; pre.z += v.z; pre.w += v.w;
        }
        const int j0 = (qbase + tid) * 4;
        const float* prep = &pre.x;
        #pragma unroll
        for (int c = 0; c < 4; ++c) {
            const int j = j0 + c;
            float pr = i2h_b[j];
            #pragma unroll
            for (int kk = 0; kk < NIN; ++kk)
                pr = fmaf(x[kk], i2h_w[j * NIN + kk], pr);
            const float hj = tanhf(pr + prep[c]);
            out[5 + j] = hj;        // user-visible h
            g_h[j]     = hj;        // aligned shadow for K3
        }
    }
}

// ============ K3: blocks 0..1023 = hebb_new (lane-contiguous); last block = heads ============
__global__ __launch_bounds__(T3)
void k3_hebb(const float* __restrict__ hebb,
             const float* __restrict__ hidden,
             const float* __restrict__ eta,
             const float* __restrict__ h2o_w,
             const float* __restrict__ h2o_b,
             const float* __restrict__ h2v_w,
             const float* __restrict__ h2v_b,
             float* __restrict__ out)
{
    const int tid = threadIdx.x;

    if (blockIdx.x == GRID3) {
        // ----- heads: 5 dot products + softmax (deterministic fixed-order reduce) -----
        __shared__ float red[16][NA + 1];
        __shared__ float logits[NA + 1];
        const int warp = tid >> 5, lane = tid & 31;
        float acc[NA + 1] = {0.f, 0.f, 0.f, 0.f, 0.f};
        #pragma unroll
        for (int k = 0; k < H / T3; ++k) {
            const int j = tid + k * T3;
            const float hv = g_h[j];
            acc[0] = fmaf(hv, h2o_w[0 * H + j], acc[0]);
            acc[1] = fmaf(hv, h2o_w[1 * H + j], acc[1]);
            acc[2] = fmaf(hv, h2o_w[2 * H + j], acc[2]);
            acc[3] = fmaf(hv, h2o_w[3 * H + j], acc[3]);
            acc[4] = fmaf(hv, h2v_w[j],         acc[4]);
        }
        #pragma unroll
        for (int a = 0; a < NA + 1; ++a) {
            #pragma unroll
            for (int o = 16; o; o >>= 1)
                acc[a] += __shfl_xor_sync(0xffffffffu, acc[a], o);
            if (lane == 0) red[warp][a] = acc[a];
        }
        __syncthreads();
        if (tid < NA + 1) {
            float s = (tid < NA) ? h2o_b[tid] : h2v_b[0];
            #pragma unroll
            for (int wp = 0; wp < 16; ++wp) s += red[wp][tid];
            logits[tid] = s;
        }
        __syncthreads();
        if (tid == 0) {
            float m = logits[0];
            #pragma unroll
            for (int a = 1; a < NA; ++a) m = fmaxf(m, logits[a]);
            float e[NA], se = 0.f;
            #pragma unroll
            for (int a = 0; a < NA; ++a) { e[a] = expf(logits[a] - m); se += e[a]; }
            const float inv = 1.f / se;
            #pragma unroll
            for (int a = 0; a < NA; ++a) out[a] = e[a] * inv;
            out[NA] = logits[NA];
        }
        return;
    }

    // ----- hebb update: 16384 elements/block, lane-contiguous (full-line LDG/STG) -----
    // reversed order so K1's last-touched (L2-hottest) hebb rows are read first
    const size_t base = (size_t)(GRID3 - 1 - blockIdx.x) * 16384;
    const float eta_v = __ldg(eta);
    const float om    = 1.f - eta_v;
    float* __restrict__ outp = out + 5 + H;     // 4B-misaligned -> scalar stores

    #pragma unroll 8
    for (int k = 0; k < 32; ++k) {
        const size_t n = base + (size_t)k * T3 + tid;
        const int i = (int)(n >> 12);           // row
        const int j = (int)(n & (H - 1));       // column
        const float hb = __ldg(hebb + n);       // mostly L2 hits (evict_last in K1)
        outp[n] = fmaf(om, hb, eta_v * __ldg(&hidden[i]) * g_h[j]);
    }
}

extern "C" void kernel_launch(void* const* d_in, const int* in_sizes, int n_in,
                              void* d_out, int out_size)
{
    const float* x      = (const float*)d_in[0];
    const float* hidden = (const float*)d_in[1];
    const float* hebb   = (const float*)d_in[2];
    const float* i2h_w  = (const float*)d_in[3];
    const float* i2h_b  = (const float*)d_in[4];
    const float* w      = (const float*)d_in[5];
    const float* alpha  = (const float*)d_in[6];
    const float* eta    = (const float*)d_in[7];
    const float* h2o_w  = (const float*)d_in[8];
    const float* h2o_b  = (const float*)d_in[9];
    const float* h2v_w  = (const float*)d_in[10];
    const float* h2v_b  = (const float*)d_in[11];
    float* out = (float*)d_out;

    k1_partials<<<GRID1, T1>>>(hidden, w, alpha, hebb);
    k2_reduce  <<<GRID2, T2>>>(x, i2h_w, i2h_b, out);
    k3_hebb    <<<GRID3 + 1, T3>>>(hebb, hidden, eta, h2o_w, h2o_b, h2v_w, h2v_b, out);
}